// round 15
// baseline (speedup 1.0000x reference)
#include <cuda_runtime.h>
#include <cuda_fp16.h>
#include <stdint.h>
#include <math.h>

// ---------------- problem constants ----------------
#define V_  32000
#define D_  512
#define L_  6
#define FF_ 2048
#define T_  2048
#define B_  2
#define S_  8
#define DS_ 32
#define K_  15

#define BT_ (B_ * T_)          // 4096 tokens
#define NC_ 32                 // scan chunks
#define TC_ (T_ / NC_)         // 64 steps per chunk

// ---------------- device scratch (no allocations allowed) ----------------
__device__ float d_X  [BT_ * D_];
__device__ float d_GV [BT_ * 2 * D_];
__device__ float d_G  [BT_ * S_];
__device__ float d_W8 [BT_ * S_];        // softmax read-weights
__device__ float d_V  [BT_ * DS_];
__device__ float d_UPc[BT_ * 2 * FF_];
__device__ float d_MEM[B_ * S_ * DS_];
__device__ float d_CHA[B_ * S_ * NC_];
__device__ float d_CHB[B_ * S_ * DS_ * NC_];
__device__ float d_CST[B_ * S_ * DS_ * NC_];

// fp16 operands, packed half2 words, row-major [row][K/2 words]
__device__ unsigned d_HN2[BT_ * D_ / 2];
__device__ unsigned d_CG2[BT_ * D_ / 2];
__device__ unsigned d_RF2[BT_ * S_ * DS_ / 2];
__device__ unsigned d_UP2[BT_ * FF_ / 2];
__device__ unsigned d_WMU[L_ * 2 * D_ * D_ / 2];
__device__ unsigned d_WMD[L_ * D_ * D_ / 2];
__device__ unsigned d_WRO[L_ * D_ * S_ * DS_ / 2];
__device__ unsigned d_WFF[L_ * 2 * FF_ * D_ / 2];   // rows 0..2047 Wgf, 2048.. Wuf per layer
__device__ unsigned d_WOF[L_ * D_ * FF_ / 2];
__device__ unsigned d_WEM[V_ * D_ / 2];

// ---------------- fp16 helpers ----------------
__device__ __forceinline__ unsigned f2h2(float x0, float x1) {
    __half2 h = __floats2half2_rn(x0, x1);
    return *reinterpret_cast<unsigned*>(&h);
}

__device__ __forceinline__ void mma_f16(float* c, const unsigned* a, unsigned b0, unsigned b1) {
    asm volatile(
        "mma.sync.aligned.m16n8k16.row.col.f32.f16.f16.f32 "
        "{%0,%1,%2,%3}, {%4,%5,%6,%7}, {%8,%9}, {%0,%1,%2,%3};"
        : "+f"(c[0]), "+f"(c[1]), "+f"(c[2]), "+f"(c[3])
        : "r"(a[0]), "r"(a[1]), "r"(a[2]), "r"(a[3]), "r"(b0), "r"(b1));
}

__device__ __forceinline__ void cp16(unsigned saddr, const void* g)
{
    asm volatile("cp.async.cg.shared.global [%0], [%1], 16;" :: "r"(saddr), "l"(g));
}

// ---------------- fp16 tensor GEMM: C[M,N] = A @ W^T (+R) ----------------
// 128x64 block tile, 4 warps (M-split), 32x64 warp tile, k-chunk 64 elems (32 words),
// 2-stage cp.async pipeline, conflict-free stride-36 smem, m16n8k16 fp16, fp32 acc.
#define ST_  36
#define AW_  (128 * ST_)           // 4608 words
#define BW_  (64 * ST_)            // 2304 words
#define STGW_ (AW_ + BW_)          // 6912 words per stage
#define SMEM_T_ (2 * STGW_ * 4)    // 55296 bytes

template<bool RES>
__global__ __launch_bounds__(128, 4)
void hgemm_kernel(const unsigned* __restrict__ A, const unsigned* __restrict__ W,
                  const float* __restrict__ R, float* __restrict__ C,
                  int M, int N, int KC)   // KC = K/64 chunks, KC >= 2
{
    extern __shared__ unsigned sm[];
    const unsigned sbase = (unsigned)__cvta_generic_to_shared(sm);
    const int tid = threadIdx.x, wid = tid >> 5, lane = tid & 31;
    const int grp = lane >> 2, kin = lane & 3;
    const int wm = wid * 32;
    const int row0 = blockIdx.y * 128, col0 = blockIdx.x * 64;
    const int Kw = KC * 32;   // words per row

    float acc[2][8][4];
#pragma unroll
    for (int i = 0; i < 2; i++)
#pragma unroll
        for (int j = 0; j < 8; j++)
#pragma unroll
            for (int r = 0; r < 4; r++) acc[i][j][r] = 0.f;

#define LOAD_STAGE(c) do {                                                    \
        const unsigned sb = sbase + (unsigned)(((c) & 1) * STGW_) * 4u;       \
        _Pragma("unroll")                                                     \
        for (int q = 0; q < 8; q++) {                                         \
            const int slot = tid + 128 * q;                                   \
            const int rr = slot >> 3, qq = slot & 7;                          \
            cp16(sb + (unsigned)(rr * ST_ + qq * 4) * 4u,                     \
                 A + (size_t)(row0 + rr) * Kw + (c) * 32 + qq * 4);           \
        }                                                                     \
        _Pragma("unroll")                                                     \
        for (int q = 0; q < 4; q++) {                                         \
            const int slot = tid + 128 * q;                                   \
            const int rr = slot >> 3, qq = slot & 7;                          \
            cp16(sb + (unsigned)(AW_ + rr * ST_ + qq * 4) * 4u,               \
                 W + (size_t)(col0 + rr) * Kw + (c) * 32 + qq * 4);           \
        }                                                                     \
        asm volatile("cp.async.commit_group;" ::: "memory");                  \
    } while (0)

    LOAD_STAGE(0);

    for (int c = 0; c < KC; c++) {
        if (c + 1 < KC) {
            LOAD_STAGE(c + 1);
            asm volatile("cp.async.wait_group 1;" ::: "memory");
        } else {
            asm volatile("cp.async.wait_group 0;" ::: "memory");
        }
        __syncthreads();

        const unsigned* sA = sm + (size_t)((c & 1) * STGW_);
        const unsigned* sB = sA + AW_;

#pragma unroll
        for (int s16 = 0; s16 < 4; s16++) {
            const int kc = s16 * 8 + kin;
            unsigned af[2][4], bf[8][2];
#pragma unroll
            for (int i = 0; i < 2; i++) {
                const int r0 = (wm + i * 16 + grp) * ST_;
                const int r1 = r0 + 8 * ST_;
                af[i][0] = sA[r0 + kc];
                af[i][1] = sA[r1 + kc];
                af[i][2] = sA[r0 + kc + 4];
                af[i][3] = sA[r1 + kc + 4];
            }
#pragma unroll
            for (int j = 0; j < 8; j++) {
                const int cb = (j * 8 + grp) * ST_;
                bf[j][0] = sB[cb + kc];
                bf[j][1] = sB[cb + kc + 4];
            }
#pragma unroll
            for (int j = 0; j < 8; j++)
#pragma unroll
                for (int i = 0; i < 2; i++)
                    mma_f16(acc[i][j], af[i], bf[j][0], bf[j][1]);
        }
        __syncthreads();
    }
#undef LOAD_STAGE

    // epilogue
    const int orow0 = row0 + wm + grp;
    const int ocol0 = col0 + 2 * kin;
#pragma unroll
    for (int i = 0; i < 2; i++) {
#pragma unroll
        for (int j = 0; j < 8; j++) {
            const size_t o0 = (size_t)(orow0 + i * 16) * N + ocol0 + j * 8;
            const size_t o1 = (size_t)(orow0 + i * 16 + 8) * N + ocol0 + j * 8;
            float2 v0 = make_float2(acc[i][j][0], acc[i][j][1]);
            float2 v1 = make_float2(acc[i][j][2], acc[i][j][3]);
            if (RES) {
                float2 r0 = *reinterpret_cast<const float2*>(R + o0);
                float2 r1 = *reinterpret_cast<const float2*>(R + o1);
                v0.x += r0.x; v0.y += r0.y;
                v1.x += r1.x; v1.y += r1.y;
            }
            *reinterpret_cast<float2*>(C + o0) = v0;
            *reinterpret_cast<float2*>(C + o1) = v1;
        }
    }
}

// ---------------- weight converter: fp32 -> packed half2 words, row remap ----------------
__global__ __launch_bounds__(256) void convert_w_kernel(
    const float* __restrict__ src, unsigned* __restrict__ dst,
    int nRows, int K, int group, int dstride, int dbase)
{
    const int Kw = K >> 1;
    long long idx = (long long)blockIdx.x * 256 + threadIdx.x;
    if (idx >= (long long)nRows * Kw) return;
    int n = (int)(idx / Kw), w = (int)(idx - (long long)n * Kw);
    int dn = (n / group) * dstride + dbase + (n % group);
    dst[(size_t)dn * Kw + w] = f2h2(src[(size_t)n * K + 2 * w], src[(size_t)n * K + 2 * w + 1]);
}

// ---------------- embed gather + rmsnorm(ln_in) -> fp32 X; fused MEM zeroing ----------------
__global__ __launch_bounds__(256) void embed_norm_kernel(
    const int* __restrict__ tokens, const float* __restrict__ embed,
    const float* __restrict__ w, float* __restrict__ out, float* __restrict__ MEM)
{
    const int bt = blockIdx.x;
    const int tid = threadIdx.x;
    if (bt == 0) { MEM[tid] = 0.f; MEM[tid + 256] = 0.f; }
    const int tok = tokens[bt];
    const float* row = embed + (size_t)tok * D_;
    float x0 = row[tid], x1 = row[tid + 256];
    __shared__ float red[256];
    red[tid] = x0 * x0 + x1 * x1;
    __syncthreads();
    for (int s = 128; s > 0; s >>= 1) {
        if (tid < s) red[tid] += red[tid + s];
        __syncthreads();
    }
    float scale = rsqrtf(red[0] / (float)D_ + 1e-6f);
    out[bt * D_ + tid]       = x0 * scale * w[tid];
    out[bt * D_ + tid + 256] = x1 * scale * w[tid + 256];
}

// ---------------- rmsnorm -> packed half2 (K=512 -> 256 words) ----------------
__global__ __launch_bounds__(256) void rmsnorm_h2_kernel(
    const float* __restrict__ X, const float* __restrict__ w, unsigned* __restrict__ O)
{
    const int bt = blockIdx.x;
    const int t = threadIdx.x;
    float x0 = X[(size_t)bt * D_ + 2 * t];
    float x1 = X[(size_t)bt * D_ + 2 * t + 1];
    __shared__ float red[256];
    red[t] = x0 * x0 + x1 * x1;
    __syncthreads();
    for (int s = 128; s > 0; s >>= 1) {
        if (t < s) red[t] += red[t + s];
        __syncthreads();
    }
    float sc = rsqrtf(red[0] / (float)D_ + 1e-6f);
    O[(size_t)bt * (D_ / 2) + t] = f2h2(x0 * sc * w[2 * t], x1 * sc * w[2 * t + 1]);
}

// ---------------- causal depthwise conv + gate -> packed half2 (K=512) ----------------
__global__ __launch_bounds__(256) void conv_gate_h2_kernel(
    const float* __restrict__ GV, const float* __restrict__ cw, unsigned* __restrict__ CG2)
{
    const int idx = blockIdx.x * 256 + threadIdx.x;
    const int w = idx & 255;
    const int bt = idx >> 8;
    const int b = bt / T_, t = bt - b * T_;
    const int d0 = 2 * w;
    float s0 = 0.f, s1 = 0.f;
#pragma unroll
    for (int j = 0; j < K_; j++) {
        int tt = t - (K_ - 1) + j;
        if (tt >= 0) {
            const float* row = GV + (size_t)(b * T_ + tt) * (2 * D_) + D_;
            s0 += row[d0]     * cw[d0 * K_ + j];
            s1 += row[d0 + 1] * cw[(d0 + 1) * K_ + j];
        }
    }
    float g0 = GV[(size_t)bt * (2 * D_) + d0];
    float g1 = GV[(size_t)bt * (2 * D_) + d0 + 1];
    CG2[(size_t)bt * (D_ / 2) + w] =
        f2h2(s0 / (1.f + expf(-g0)), s1 / (1.f + expf(-g1)));
}

// ---------------- fused rmsnorm + small projections + read-softmax ----------------
// Computes hm = rmsnorm(X, ln_mem) in smem, then g (sigmoid), v, and softmax(rq.hm).
__global__ __launch_bounds__(256) void norm_proj_kernel(
    const float* __restrict__ X, const float* __restrict__ lnw,
    const float* __restrict__ wg, const float* __restrict__ rqw, const float* __restrict__ wv,
    float* __restrict__ G, float* __restrict__ W8, float* __restrict__ Vv)
{
    const int bt = blockIdx.x;
    const int tid = threadIdx.x;
    __shared__ float h[D_];
    __shared__ float red[256];
    __shared__ float qsh[S_];
    float x0 = X[(size_t)bt * D_ + tid];
    float x1 = X[(size_t)bt * D_ + tid + 256];
    red[tid] = x0 * x0 + x1 * x1;
    __syncthreads();
    for (int s = 128; s > 0; s >>= 1) {
        if (tid < s) red[tid] += red[tid + s];
        __syncthreads();
    }
    float sc = rsqrtf(red[0] / (float)D_ + 1e-6f);
    h[tid]       = x0 * sc * lnw[tid];
    h[tid + 256] = x1 * sc * lnw[tid + 256];
    __syncthreads();

    const int warp = tid >> 5, lane = tid & 31;
    for (int o = warp; o < S_ + S_ + DS_; o += 8) {
        const float* wrow;
        if (o < S_) wrow = wg + o * D_;
        else if (o < 2 * S_) wrow = rqw + (o - S_) * D_;
        else wrow = wv + (o - 2 * S_) * D_;
        float s = 0.f;
#pragma unroll
        for (int k = lane; k < D_; k += 32) s += h[k] * wrow[k];
#pragma unroll
        for (int off = 16; off > 0; off >>= 1) s += __shfl_down_sync(0xffffffffu, s, off);
        if (lane == 0) {
            if (o < S_) G[bt * S_ + o] = 1.f / (1.f + expf(-s));
            else if (o < 2 * S_) qsh[o - S_] = s;
            else Vv[bt * DS_ + (o - 2 * S_)] = s;
        }
    }
    __syncthreads();
    if (tid < S_) {
        float mx = qsh[0];
#pragma unroll
        for (int i = 1; i < S_; i++) mx = fmaxf(mx, qsh[i]);
        float den = 0.f;
#pragma unroll
        for (int i = 0; i < S_; i++) den += expf(qsh[i] - mx);
        W8[bt * S_ + tid] = expf(qsh[tid] - mx) / den;
    }
}

// ---------------- chunked linear-recurrence scan ----------------
__global__ __launch_bounds__(256) void scan_pass1_kernel(
    const float* __restrict__ G, const float* __restrict__ Vv,
    float* __restrict__ CHA, float* __restrict__ CHB)
{
    const int idx = blockIdx.x * 256 + threadIdx.x;
    const int ds = idx % DS_;
    const int s  = (idx / DS_) % S_;
    const int c  = (idx / (DS_ * S_)) % NC_;
    const int b  = idx / (DS_ * S_ * NC_);
    float A = 1.f, Bv = 0.f;
    const int t0 = c * TC_;
    for (int t = t0; t < t0 + TC_; t++) {
        float g = G[(size_t)(b * T_ + t) * S_ + s];
        float a = 1.f - g;
        float bb = g * Vv[(size_t)(b * T_ + t) * DS_ + ds];
        A = a * A;
        Bv = a * Bv + bb;
    }
    CHB[((size_t)(b * S_ + s) * DS_ + ds) * NC_ + c] = Bv;
    if (ds == 0) CHA[(size_t)(b * S_ + s) * NC_ + c] = A;
}

__global__ __launch_bounds__(512) void scan_pass2_kernel(
    const float* __restrict__ CHA, const float* __restrict__ CHB,
    float* __restrict__ MEM, float* __restrict__ CST)
{
    const int idx = threadIdx.x;
    const int ds = idx % DS_;
    const int s  = (idx / DS_) % S_;
    const int b  = idx / (DS_ * S_);
    float st = MEM[idx];
    for (int c = 0; c < NC_; c++) {
        CST[((size_t)(b * S_ + s) * DS_ + ds) * NC_ + c] = st;
        float A = CHA[(size_t)(b * S_ + s) * NC_ + c];
        float Bv = CHB[((size_t)(b * S_ + s) * DS_ + ds) * NC_ + c];
        st = A * st + Bv;
    }
    MEM[idx] = st;
}

// ---------------- fused scan pass3 + read-weight apply -> packed half2 RF2 ----------------
// Threads over (b, c, s, dp) with dp = pair of ds. Writes RF2 directly.
__global__ __launch_bounds__(256) void scan3_rf_kernel(
    const float* __restrict__ G, const float* __restrict__ Vv,
    const float* __restrict__ CST, const float* __restrict__ W8,
    unsigned* __restrict__ RF2)
{
    const int idx = blockIdx.x * 256 + threadIdx.x;   // B_*S_*NC_*16 = 8192
    const int dp = idx & 15;
    const int s  = (idx >> 4) & (S_ - 1);
    const int c  = (idx >> 7) & (NC_ - 1);
    const int b  = idx >> 12;
    const int ds0 = 2 * dp;
    float m0 = CST[((size_t)(b * S_ + s) * DS_ + ds0) * NC_ + c];
    float m1 = CST[((size_t)(b * S_ + s) * DS_ + ds0 + 1) * NC_ + c];
    const int t0 = c * TC_;
    for (int t = t0; t < t0 + TC_; t++) {
        const int bt = b * T_ + t;
        float g = G[(size_t)bt * S_ + s];
        float a = 1.f - g;
        m0 = a * m0 + g * Vv[(size_t)bt * DS_ + ds0];
        m1 = a * m1 + g * Vv[(size_t)bt * DS_ + ds0 + 1];
        float wgt = W8[(size_t)bt * S_ + s];
        RF2[(size_t)bt * 128 + s * 16 + dp] = f2h2(wgt * m0, wgt * m1);
    }
}

// ---------------- silu(gate)*up -> packed half2 (K=2048 -> 1024 words) ----------------
__global__ __launch_bounds__(256) void silu_h2_kernel(
    const float* __restrict__ UPc, unsigned* __restrict__ UP2)
{
    const int idx = blockIdx.x * 256 + threadIdx.x;   // BT_ * 1024 words
    const int bt = idx >> 10;
    const int w = idx & 1023;
    const int f0 = 2 * w;
    float a0 = UPc[(size_t)bt * 4096 + f0];
    float a1 = UPc[(size_t)bt * 4096 + f0 + 1];
    float b0 = UPc[(size_t)bt * 4096 + 2048 + f0];
    float b1 = UPc[(size_t)bt * 4096 + 2048 + f0 + 1];
    UP2[(size_t)bt * (FF_ / 2) + w] =
        f2h2(a0 / (1.f + expf(-a0)) * b0, a1 / (1.f + expf(-a1)) * b1);
}

// ---------------- host orchestration ----------------
static void* devptr(const void* symbol) {
    void* p = nullptr;
    cudaGetSymbolAddress(&p, symbol);
    return p;
}

static inline int cblocks(long long threads) { return (int)((threads + 255) / 256); }

extern "C" void kernel_launch(void* const* d_in, const int* in_sizes, int n_in,
                              void* d_out, int out_size)
{
    const int*   tokens    = (const int*)  d_in[0];
    const float* embed     = (const float*)d_in[1];
    const float* ln_in     = (const float*)d_in[2];
    const float* ln1       = (const float*)d_in[3];
    const float* mixer_up  = (const float*)d_in[4];
    const float* conv_w    = (const float*)d_in[5];
    const float* mixer_down= (const float*)d_in[6];
    const float* ln_mem    = (const float*)d_in[7];
    const float* wg        = (const float*)d_in[8];
    const float* wv        = (const float*)d_in[9];
    const float* rq        = (const float*)d_in[10];
    const float* ro        = (const float*)d_in[11];
    const float* ln2       = (const float*)d_in[12];
    const float* Wgf       = (const float*)d_in[13];
    const float* Wuf       = (const float*)d_in[14];
    const float* Wof       = (const float*)d_in[15];
    const float* ln_out    = (const float*)d_in[16];
    float* out = (float*)d_out;

    float* X   = (float*)devptr(d_X);
    float* GV  = (float*)devptr(d_GV);
    float* G   = (float*)devptr(d_G);
    float* W8  = (float*)devptr(d_W8);
    float* Vv  = (float*)devptr(d_V);
    float* UPc = (float*)devptr(d_UPc);
    float* MEM = (float*)devptr(d_MEM);
    float* CHA = (float*)devptr(d_CHA);
    float* CHB = (float*)devptr(d_CHB);
    float* CST = (float*)devptr(d_CST);

    unsigned* HN2 = (unsigned*)devptr(d_HN2);
    unsigned* CG2 = (unsigned*)devptr(d_CG2);
    unsigned* RF2 = (unsigned*)devptr(d_RF2);
    unsigned* UP2 = (unsigned*)devptr(d_UP2);
    unsigned* WMU = (unsigned*)devptr(d_WMU);
    unsigned* WMD = (unsigned*)devptr(d_WMD);
    unsigned* WRO = (unsigned*)devptr(d_WRO);
    unsigned* WFF = (unsigned*)devptr(d_WFF);
    unsigned* WOF = (unsigned*)devptr(d_WOF);
    unsigned* WEM = (unsigned*)devptr(d_WEM);

    cudaFuncSetAttribute(hgemm_kernel<false>, cudaFuncAttributeMaxDynamicSharedMemorySize, SMEM_T_);
    cudaFuncSetAttribute(hgemm_kernel<true>,  cudaFuncAttributeMaxDynamicSharedMemorySize, SMEM_T_);

    // packed words per row
    const size_t RWD  = D_ / 2;        // 256
    const size_t RWRO = S_ * DS_ / 2;  // 128
    const size_t RWFF = FF_ / 2;       // 1024

    // launch order: [0] convert WMU, [1] embed_norm(+MEM zero), [2] rmsnorm_h2,
    // [3] first hgemm  <- captured by ncu
    convert_w_kernel<<<cblocks((long long)L_ * 2 * D_ * RWD), 256>>>(
        mixer_up, WMU, L_ * 2 * D_, D_, L_ * 2 * D_, L_ * 2 * D_, 0);
    embed_norm_kernel<<<BT_, 256>>>(tokens, embed, ln_in, X, MEM);

    for (int i = 0; i < L_; i++) {
        const float* ln1_i = ln1 + i * D_;
        const float* cw_i  = conv_w + (size_t)i * D_ * K_;
        const float* lnm_i = ln_mem + i * D_;
        const float* wg_i  = wg + (size_t)i * S_ * D_;
        const float* wv_i  = wv + (size_t)i * DS_ * D_;
        const float* rq_i  = rq + (size_t)i * S_ * D_;
        const float* ln2_i = ln2 + i * D_;

        const unsigned* wmu_i = WMU + (size_t)i * 2 * D_ * RWD;
        const unsigned* wmd_i = WMD + (size_t)i * D_ * RWD;
        const unsigned* wro_i = WRO + (size_t)i * D_ * RWRO;
        const unsigned* wff_i = WFF + (size_t)i * 2 * FF_ * RWD;
        const unsigned* wof_i = WOF + (size_t)i * D_ * RWFF;

        // mixer branch
        rmsnorm_h2_kernel<<<BT_, 256>>>(X, ln1_i, HN2);
        hgemm_kernel<false><<<dim3(2 * D_ / 64, BT_ / 128), 128, SMEM_T_>>>(
            HN2, wmu_i, nullptr, GV, BT_, 2 * D_, D_ / 64);

        if (i == 0) {
            convert_w_kernel<<<cblocks((long long)L_ * D_ * RWD), 256>>>(
                mixer_down, WMD, L_ * D_, D_, L_ * D_, L_ * D_, 0);
            convert_w_kernel<<<cblocks((long long)L_ * D_ * RWRO), 256>>>(
                ro, WRO, L_ * D_, S_ * DS_, L_ * D_, L_ * D_, 0);
            convert_w_kernel<<<cblocks((long long)L_ * FF_ * RWD), 256>>>(
                Wgf, WFF, L_ * FF_, D_, FF_, 2 * FF_, 0);
            convert_w_kernel<<<cblocks((long long)L_ * FF_ * RWD), 256>>>(
                Wuf, WFF, L_ * FF_, D_, FF_, 2 * FF_, FF_);
            convert_w_kernel<<<cblocks((long long)L_ * D_ * RWFF), 256>>>(
                Wof, WOF, L_ * D_, FF_, L_ * D_, L_ * D_, 0);
            convert_w_kernel<<<cblocks((long long)V_ * RWD), 256>>>(
                embed, WEM, V_, D_, V_, V_, 0);
        }

        conv_gate_h2_kernel<<<BT_, 256>>>(GV, cw_i, CG2);
        hgemm_kernel<true><<<dim3(D_ / 64, BT_ / 128), 128, SMEM_T_>>>(
            CG2, wmd_i, X, X, BT_, D_, D_ / 64);

        // story memory branch (fused)
        norm_proj_kernel<<<BT_, 256>>>(X, lnm_i, wg_i, rq_i, wv_i, G, W8, Vv);
        scan_pass1_kernel<<<B_ * S_ * DS_ * NC_ / 256, 256>>>(G, Vv, CHA, CHB);
        scan_pass2_kernel<<<1, B_ * S_ * DS_>>>(CHA, CHB, MEM, CST);
        scan3_rf_kernel<<<B_ * S_ * NC_ * 16 / 256, 256>>>(G, Vv, CST, W8, RF2);
        hgemm_kernel<true><<<dim3(D_ / 64, BT_ / 128), 128, SMEM_T_>>>(
            RF2, wro_i, X, X, BT_, D_, S_ * DS_ / 64);

        // FFN branch (fused gate+up GEMM, N = 4096)
        rmsnorm_h2_kernel<<<BT_, 256>>>(X, ln2_i, HN2);
        hgemm_kernel<false><<<dim3(2 * FF_ / 64, BT_ / 128), 128, SMEM_T_>>>(
            HN2, wff_i, nullptr, UPc, BT_, 2 * FF_, D_ / 64);
        silu_h2_kernel<<<cblocks((long long)BT_ * (FF_ / 2)), 256>>>(UPc, UP2);
        hgemm_kernel<true><<<dim3(D_ / 64, BT_ / 128), 128, SMEM_T_>>>(
            UP2, wof_i, X, X, BT_, D_, FF_ / 64);
    }

    // tied head
    rmsnorm_h2_kernel<<<BT_, 256>>>(X, ln_out, HN2);
    hgemm_kernel<false><<<dim3(V_ / 64, BT_ / 128), 128, SMEM_T_>>>(
        HN2, WEM, nullptr, out, BT_, V_, D_ / 64);
}

// round 16
// speedup vs baseline: 1.0484x; 1.0484x over previous
#include <cuda_runtime.h>
#include <cuda_fp16.h>
#include <stdint.h>
#include <math.h>

// ---------------- problem constants ----------------
#define V_  32000
#define D_  512
#define L_  6
#define FF_ 2048
#define T_  2048
#define B_  2
#define S_  8
#define DS_ 32
#define K_  15

#define BT_ (B_ * T_)          // 4096 tokens
#define NC_ 32                 // scan chunks
#define TC_ (T_ / NC_)         // 64 steps per chunk

// ---------------- device scratch (no allocations allowed) ----------------
__device__ float d_X  [BT_ * D_];
__device__ float d_HN [BT_ * D_];
__device__ float d_GV [BT_ * 2 * D_];
__device__ float d_G  [BT_ * S_];
__device__ float d_RQ [BT_ * S_];
__device__ float d_V  [BT_ * DS_];
__device__ float d_MS [BT_ * S_ * DS_];
__device__ float d_MEM[B_ * S_ * DS_];
__device__ float d_CHA[B_ * S_ * NC_];
__device__ float d_CHB[B_ * S_ * DS_ * NC_];
__device__ float d_CST[B_ * S_ * DS_ * NC_];

// fp16 operands, packed half2 words, row-major [row][K/2 words]
__device__ unsigned d_HN2[BT_ * D_ / 2];
__device__ unsigned d_CG2[BT_ * D_ / 2];
__device__ unsigned d_RF2[BT_ * S_ * DS_ / 2];
__device__ unsigned d_UP2[BT_ * FF_ / 2];
__device__ unsigned d_WMU[L_ * 2 * D_ * D_ / 2];
__device__ unsigned d_WMD[L_ * D_ * D_ / 2];
__device__ unsigned d_WRO[L_ * D_ * S_ * DS_ / 2];
__device__ unsigned d_WFF[L_ * 2 * FF_ * D_ / 2];   // INTERLEAVED: row 2f = Wgf_f, 2f+1 = Wuf_f
__device__ unsigned d_WOF[L_ * D_ * FF_ / 2];
__device__ unsigned d_WEM[V_ * D_ / 2];

// ---------------- fp16 helpers ----------------
__device__ __forceinline__ unsigned f2h2(float x0, float x1) {
    __half2 h = __floats2half2_rn(x0, x1);
    return *reinterpret_cast<unsigned*>(&h);
}

__device__ __forceinline__ void mma_f16(float* c, const unsigned* a, unsigned b0, unsigned b1) {
    asm volatile(
        "mma.sync.aligned.m16n8k16.row.col.f32.f16.f16.f32 "
        "{%0,%1,%2,%3}, {%4,%5,%6,%7}, {%8,%9}, {%0,%1,%2,%3};"
        : "+f"(c[0]), "+f"(c[1]), "+f"(c[2]), "+f"(c[3])
        : "r"(a[0]), "r"(a[1]), "r"(a[2]), "r"(a[3]), "r"(b0), "r"(b1));
}

__device__ __forceinline__ void cp16(unsigned saddr, const void* g)
{
    asm volatile("cp.async.cg.shared.global [%0], [%1], 16;" :: "r"(saddr), "l"(g));
}

// ---------------- fp16 tensor GEMM: C[M,N] = A @ W^T ----------------
// EPI: 0 = plain store, 1 = residual add, 2 = silu-combine adjacent column
// pairs (gate,up) -> __half store into C viewed as half[M][N/2].
// 128x64 block tile, 4 warps (M-split), 32x64 warp tile, k-chunk 64 elems,
// 2-stage cp.async pipeline, conflict-free stride-36 smem, m16n8k16, fp32 acc.
#define ST_  36
#define AW_  (128 * ST_)           // 4608 words
#define BW_  (64 * ST_)            // 2304 words
#define STGW_ (AW_ + BW_)          // 6912 words per stage
#define SMEM_T_ (2 * STGW_ * 4)    // 55296 bytes

template<int EPI>
__global__ __launch_bounds__(128, 4)
void hgemm_kernel(const unsigned* __restrict__ A, const unsigned* __restrict__ W,
                  const float* __restrict__ R, float* __restrict__ C,
                  int M, int N, int KC)   // KC = K/64 chunks, KC >= 2
{
    extern __shared__ unsigned sm[];
    const unsigned sbase = (unsigned)__cvta_generic_to_shared(sm);
    const int tid = threadIdx.x, wid = tid >> 5, lane = tid & 31;
    const int grp = lane >> 2, kin = lane & 3;
    const int wm = wid * 32;
    const int row0 = blockIdx.y * 128, col0 = blockIdx.x * 64;
    const int Kw = KC * 32;   // words per row

    float acc[2][8][4];
#pragma unroll
    for (int i = 0; i < 2; i++)
#pragma unroll
        for (int j = 0; j < 8; j++)
#pragma unroll
            for (int r = 0; r < 4; r++) acc[i][j][r] = 0.f;

#define LOAD_STAGE(c) do {                                                    \
        const unsigned sb = sbase + (unsigned)(((c) & 1) * STGW_) * 4u;       \
        _Pragma("unroll")                                                     \
        for (int q = 0; q < 8; q++) {                                         \
            const int slot = tid + 128 * q;                                   \
            const int rr = slot >> 3, qq = slot & 7;                          \
            cp16(sb + (unsigned)(rr * ST_ + qq * 4) * 4u,                     \
                 A + (size_t)(row0 + rr) * Kw + (c) * 32 + qq * 4);           \
        }                                                                     \
        _Pragma("unroll")                                                     \
        for (int q = 0; q < 4; q++) {                                         \
            const int slot = tid + 128 * q;                                   \
            const int rr = slot >> 3, qq = slot & 7;                          \
            cp16(sb + (unsigned)(AW_ + rr * ST_ + qq * 4) * 4u,               \
                 W + (size_t)(col0 + rr) * Kw + (c) * 32 + qq * 4);           \
        }                                                                     \
        asm volatile("cp.async.commit_group;" ::: "memory");                  \
    } while (0)

    LOAD_STAGE(0);

    for (int c = 0; c < KC; c++) {
        if (c + 1 < KC) {
            LOAD_STAGE(c + 1);
            asm volatile("cp.async.wait_group 1;" ::: "memory");
        } else {
            asm volatile("cp.async.wait_group 0;" ::: "memory");
        }
        __syncthreads();

        const unsigned* sA = sm + (size_t)((c & 1) * STGW_);
        const unsigned* sB = sA + AW_;

#pragma unroll
        for (int s16 = 0; s16 < 4; s16++) {
            const int kc = s16 * 8 + kin;
            unsigned af[2][4], bf[8][2];
#pragma unroll
            for (int i = 0; i < 2; i++) {
                const int r0 = (wm + i * 16 + grp) * ST_;
                const int r1 = r0 + 8 * ST_;
                af[i][0] = sA[r0 + kc];
                af[i][1] = sA[r1 + kc];
                af[i][2] = sA[r0 + kc + 4];
                af[i][3] = sA[r1 + kc + 4];
            }
#pragma unroll
            for (int j = 0; j < 8; j++) {
                const int cb = (j * 8 + grp) * ST_;
                bf[j][0] = sB[cb + kc];
                bf[j][1] = sB[cb + kc + 4];
            }
#pragma unroll
            for (int j = 0; j < 8; j++)
#pragma unroll
                for (int i = 0; i < 2; i++)
                    mma_f16(acc[i][j], af[i], bf[j][0], bf[j][1]);
        }
        __syncthreads();
    }
#undef LOAD_STAGE

    // epilogue
    const int orow0 = row0 + wm + grp;
    const int ocol0 = col0 + 2 * kin;
    if (EPI == 2) {
        __half* H = reinterpret_cast<__half*>(C);
        const int hN = N >> 1;
#pragma unroll
        for (int i = 0; i < 2; i++) {
#pragma unroll
            for (int j = 0; j < 8; j++) {
                const int f = (ocol0 + j * 8) >> 1;
                float g0 = acc[i][j][0], u0 = acc[i][j][1];
                float g1 = acc[i][j][2], u1 = acc[i][j][3];
                H[(size_t)(orow0 + i * 16) * hN + f] =
                    __float2half_rn(g0 / (1.f + expf(-g0)) * u0);
                H[(size_t)(orow0 + i * 16 + 8) * hN + f] =
                    __float2half_rn(g1 / (1.f + expf(-g1)) * u1);
            }
        }
    } else {
#pragma unroll
        for (int i = 0; i < 2; i++) {
#pragma unroll
            for (int j = 0; j < 8; j++) {
                const size_t o0 = (size_t)(orow0 + i * 16) * N + ocol0 + j * 8;
                const size_t o1 = (size_t)(orow0 + i * 16 + 8) * N + ocol0 + j * 8;
                float2 v0 = make_float2(acc[i][j][0], acc[i][j][1]);
                float2 v1 = make_float2(acc[i][j][2], acc[i][j][3]);
                if (EPI == 1) {
                    float2 r0 = *reinterpret_cast<const float2*>(R + o0);
                    float2 r1 = *reinterpret_cast<const float2*>(R + o1);
                    v0.x += r0.x; v0.y += r0.y;
                    v1.x += r1.x; v1.y += r1.y;
                }
                *reinterpret_cast<float2*>(C + o0) = v0;
                *reinterpret_cast<float2*>(C + o1) = v1;
            }
        }
    }
}

// ---------------- weight converter: fp32 -> packed half2 words, row remap ----------------
// dest row = (n/group)*dstride + dbase + n%group
__global__ __launch_bounds__(256) void convert_w_kernel(
    const float* __restrict__ src, unsigned* __restrict__ dst,
    int nRows, int K, int group, int dstride, int dbase)
{
    const int Kw = K >> 1;
    long long idx = (long long)blockIdx.x * 256 + threadIdx.x;
    if (idx >= (long long)nRows * Kw) return;
    int n = (int)(idx / Kw), w = (int)(idx - (long long)n * Kw);
    int dn = (n / group) * dstride + dbase + (n % group);
    dst[(size_t)dn * Kw + w] = f2h2(src[(size_t)n * K + 2 * w], src[(size_t)n * K + 2 * w + 1]);
}

// ---------------- embed gather + rmsnorm(ln_in) -> fp32 X; fused MEM zeroing ----------------
__global__ __launch_bounds__(256) void embed_norm_kernel(
    const int* __restrict__ tokens, const float* __restrict__ embed,
    const float* __restrict__ w, float* __restrict__ out, float* __restrict__ MEM)
{
    const int bt = blockIdx.x;
    const int tid = threadIdx.x;
    if (bt == 0) { MEM[tid] = 0.f; MEM[tid + 256] = 0.f; }
    const int tok = tokens[bt];
    const float* row = embed + (size_t)tok * D_;
    float x0 = row[tid], x1 = row[tid + 256];
    __shared__ float red[256];
    red[tid] = x0 * x0 + x1 * x1;
    __syncthreads();
    for (int s = 128; s > 0; s >>= 1) {
        if (tid < s) red[tid] += red[tid + s];
        __syncthreads();
    }
    float scale = rsqrtf(red[0] / (float)D_ + 1e-6f);
    out[bt * D_ + tid]       = x0 * scale * w[tid];
    out[bt * D_ + tid + 256] = x1 * scale * w[tid + 256];
}

// ---------------- rmsnorm -> fp32 (story-memory branch) ----------------
__global__ __launch_bounds__(256) void rmsnorm_kernel(
    const float* __restrict__ X, const float* __restrict__ w, float* __restrict__ O)
{
    const int bt = blockIdx.x;
    const int tid = threadIdx.x;
    float x0 = X[bt * D_ + tid], x1 = X[bt * D_ + tid + 256];
    __shared__ float red[256];
    red[tid] = x0 * x0 + x1 * x1;
    __syncthreads();
    for (int s = 128; s > 0; s >>= 1) {
        if (tid < s) red[tid] += red[tid + s];
        __syncthreads();
    }
    float scale = rsqrtf(red[0] / (float)D_ + 1e-6f);
    O[bt * D_ + tid]       = x0 * scale * w[tid];
    O[bt * D_ + tid + 256] = x1 * scale * w[tid + 256];
}

// ---------------- rmsnorm -> packed half2 (K=512 -> 256 words) ----------------
__global__ __launch_bounds__(256) void rmsnorm_h2_kernel(
    const float* __restrict__ X, const float* __restrict__ w, unsigned* __restrict__ O)
{
    const int bt = blockIdx.x;
    const int t = threadIdx.x;
    float x0 = X[(size_t)bt * D_ + 2 * t];
    float x1 = X[(size_t)bt * D_ + 2 * t + 1];
    __shared__ float red[256];
    red[t] = x0 * x0 + x1 * x1;
    __syncthreads();
    for (int s = 128; s > 0; s >>= 1) {
        if (t < s) red[t] += red[t + s];
        __syncthreads();
    }
    float sc = rsqrtf(red[0] / (float)D_ + 1e-6f);
    O[(size_t)bt * (D_ / 2) + t] = f2h2(x0 * sc * w[2 * t], x1 * sc * w[2 * t + 1]);
}

// ---------------- causal depthwise conv + gate -> packed half2 (K=512) ----------------
__global__ __launch_bounds__(256) void conv_gate_h2_kernel(
    const float* __restrict__ GV, const float* __restrict__ cw, unsigned* __restrict__ CG2)
{
    const int idx = blockIdx.x * 256 + threadIdx.x;
    const int w = idx & 255;
    const int bt = idx >> 8;
    const int b = bt / T_, t = bt - b * T_;
    const int d0 = 2 * w;
    float s0 = 0.f, s1 = 0.f;
#pragma unroll
    for (int j = 0; j < K_; j++) {
        int tt = t - (K_ - 1) + j;
        if (tt >= 0) {
            const float* row = GV + (size_t)(b * T_ + tt) * (2 * D_) + D_;
            s0 += row[d0]     * cw[d0 * K_ + j];
            s1 += row[d0 + 1] * cw[(d0 + 1) * K_ + j];
        }
    }
    float g0 = GV[(size_t)bt * (2 * D_) + d0];
    float g1 = GV[(size_t)bt * (2 * D_) + d0 + 1];
    CG2[(size_t)bt * (D_ / 2) + w] =
        f2h2(s0 / (1.f + expf(-g0)), s1 / (1.f + expf(-g1)));
}

// ---------------- small projections ----------------
__global__ __launch_bounds__(256) void smallproj_kernel(
    const float* __restrict__ HN, const float* __restrict__ wg,
    const float* __restrict__ rqw, const float* __restrict__ wv,
    float* __restrict__ G, float* __restrict__ RQ, float* __restrict__ Vv)
{
    const int bt = blockIdx.x;
    const int tid = threadIdx.x;
    __shared__ float h[D_];
    h[tid] = HN[bt * D_ + tid];
    h[tid + 256] = HN[bt * D_ + tid + 256];
    __syncthreads();
    const int warp = tid >> 5, lane = tid & 31;
    for (int o = warp; o < S_ + S_ + DS_; o += 8) {
        const float* wrow;
        if (o < S_) wrow = wg + o * D_;
        else if (o < 2 * S_) wrow = rqw + (o - S_) * D_;
        else wrow = wv + (o - 2 * S_) * D_;
        float s = 0.f;
#pragma unroll
        for (int k = lane; k < D_; k += 32) s += h[k] * wrow[k];
#pragma unroll
        for (int off = 16; off > 0; off >>= 1) s += __shfl_down_sync(0xffffffffu, s, off);
        if (lane == 0) {
            if (o < S_) G[bt * S_ + o] = 1.f / (1.f + expf(-s));
            else if (o < 2 * S_) RQ[bt * S_ + (o - S_)] = s;
            else Vv[bt * DS_ + (o - 2 * S_)] = s;
        }
    }
}

// ---------------- chunked linear-recurrence scan ----------------
__global__ __launch_bounds__(256) void scan_pass1_kernel(
    const float* __restrict__ G, const float* __restrict__ Vv,
    float* __restrict__ CHA, float* __restrict__ CHB)
{
    const int idx = blockIdx.x * 256 + threadIdx.x;
    const int ds = idx % DS_;
    const int s  = (idx / DS_) % S_;
    const int c  = (idx / (DS_ * S_)) % NC_;
    const int b  = idx / (DS_ * S_ * NC_);
    float A = 1.f, Bv = 0.f;
    const int t0 = c * TC_;
    for (int t = t0; t < t0 + TC_; t++) {
        float g = G[(size_t)(b * T_ + t) * S_ + s];
        float a = 1.f - g;
        float bb = g * Vv[(size_t)(b * T_ + t) * DS_ + ds];
        A = a * A;
        Bv = a * Bv + bb;
    }
    CHB[((size_t)(b * S_ + s) * DS_ + ds) * NC_ + c] = Bv;
    if (ds == 0) CHA[(size_t)(b * S_ + s) * NC_ + c] = A;
}

__global__ __launch_bounds__(512) void scan_pass2_kernel(
    const float* __restrict__ CHA, const float* __restrict__ CHB,
    float* __restrict__ MEM, float* __restrict__ CST)
{
    const int idx = threadIdx.x;
    const int ds = idx % DS_;
    const int s  = (idx / DS_) % S_;
    const int b  = idx / (DS_ * S_);
    float st = MEM[idx];
    for (int c = 0; c < NC_; c++) {
        CST[((size_t)(b * S_ + s) * DS_ + ds) * NC_ + c] = st;
        float A = CHA[(size_t)(b * S_ + s) * NC_ + c];
        float Bv = CHB[((size_t)(b * S_ + s) * DS_ + ds) * NC_ + c];
        st = A * st + Bv;
    }
    MEM[idx] = st;
}

__global__ __launch_bounds__(256) void scan_pass3_kernel(
    const float* __restrict__ G, const float* __restrict__ Vv,
    const float* __restrict__ CST, float* __restrict__ MS)
{
    const int idx = blockIdx.x * 256 + threadIdx.x;
    const int ds = idx % DS_;
    const int s  = (idx / DS_) % S_;
    const int c  = (idx / (DS_ * S_)) % NC_;
    const int b  = idx / (DS_ * S_ * NC_);
    float m = CST[((size_t)(b * S_ + s) * DS_ + ds) * NC_ + c];
    const int t0 = c * TC_;
    for (int t = t0; t < t0 + TC_; t++) {
        float g = G[(size_t)(b * T_ + t) * S_ + s];
        float bb = g * Vv[(size_t)(b * T_ + t) * DS_ + ds];
        m = (1.f - g) * m + bb;
        MS[(size_t)(b * T_ + t) * (S_ * DS_) + s * DS_ + ds] = m;
    }
}

// ---------------- softmax read * mem_stack -> packed half2 (K=256 -> 128 words) ----------------
__global__ __launch_bounds__(128) void rf_h2_kernel(
    const float* __restrict__ RQ, const float* __restrict__ MS, unsigned* __restrict__ RF2)
{
    const int bt = blockIdx.x;
    const int t = threadIdx.x;   // word index 0..127
    __shared__ float q[S_];
    if (t < S_) q[t] = RQ[bt * S_ + t];
    __syncthreads();
    float mx = q[0];
#pragma unroll
    for (int i = 1; i < S_; i++) mx = fmaxf(mx, q[i]);
    float den = 0.f;
#pragma unroll
    for (int i = 0; i < S_; i++) den += expf(q[i] - mx);
    const int e0 = 2 * t;
    const int s = e0 >> 5;
    float wgt = expf(q[s] - mx) / den;
    RF2[(size_t)bt * 128 + t] =
        f2h2(wgt * MS[(size_t)bt * 256 + e0], wgt * MS[(size_t)bt * 256 + e0 + 1]);
}

// ---------------- host orchestration ----------------
static void* devptr(const void* symbol) {
    void* p = nullptr;
    cudaGetSymbolAddress(&p, symbol);
    return p;
}

static inline int cblocks(long long threads) { return (int)((threads + 255) / 256); }

extern "C" void kernel_launch(void* const* d_in, const int* in_sizes, int n_in,
                              void* d_out, int out_size)
{
    const int*   tokens    = (const int*)  d_in[0];
    const float* embed     = (const float*)d_in[1];
    const float* ln_in     = (const float*)d_in[2];
    const float* ln1       = (const float*)d_in[3];
    const float* mixer_up  = (const float*)d_in[4];
    const float* conv_w    = (const float*)d_in[5];
    const float* mixer_down= (const float*)d_in[6];
    const float* ln_mem    = (const float*)d_in[7];
    const float* wg        = (const float*)d_in[8];
    const float* wv        = (const float*)d_in[9];
    const float* rq        = (const float*)d_in[10];
    const float* ro        = (const float*)d_in[11];
    const float* ln2       = (const float*)d_in[12];
    const float* Wgf       = (const float*)d_in[13];
    const float* Wuf       = (const float*)d_in[14];
    const float* Wof       = (const float*)d_in[15];
    const float* ln_out    = (const float*)d_in[16];
    float* out = (float*)d_out;

    float* X   = (float*)devptr(d_X);
    float* HN  = (float*)devptr(d_HN);
    float* GV  = (float*)devptr(d_GV);
    float* G   = (float*)devptr(d_G);
    float* RQ  = (float*)devptr(d_RQ);
    float* Vv  = (float*)devptr(d_V);
    float* MS  = (float*)devptr(d_MS);
    float* MEM = (float*)devptr(d_MEM);
    float* CHA = (float*)devptr(d_CHA);
    float* CHB = (float*)devptr(d_CHB);
    float* CST = (float*)devptr(d_CST);

    unsigned* HN2 = (unsigned*)devptr(d_HN2);
    unsigned* CG2 = (unsigned*)devptr(d_CG2);
    unsigned* RF2 = (unsigned*)devptr(d_RF2);
    unsigned* UP2 = (unsigned*)devptr(d_UP2);
    unsigned* WMU = (unsigned*)devptr(d_WMU);
    unsigned* WMD = (unsigned*)devptr(d_WMD);
    unsigned* WRO = (unsigned*)devptr(d_WRO);
    unsigned* WFF = (unsigned*)devptr(d_WFF);
    unsigned* WOF = (unsigned*)devptr(d_WOF);
    unsigned* WEM = (unsigned*)devptr(d_WEM);

    cudaFuncSetAttribute(hgemm_kernel<0>, cudaFuncAttributeMaxDynamicSharedMemorySize, SMEM_T_);
    cudaFuncSetAttribute(hgemm_kernel<1>, cudaFuncAttributeMaxDynamicSharedMemorySize, SMEM_T_);
    cudaFuncSetAttribute(hgemm_kernel<2>, cudaFuncAttributeMaxDynamicSharedMemorySize, SMEM_T_);

    // packed words per row
    const size_t RWD  = D_ / 2;        // 256
    const size_t RWRO = S_ * DS_ / 2;  // 128
    const size_t RWFF = FF_ / 2;       // 1024

    // launch order: [0] convert WMU, [1] embed_norm(+MEM zero), [2] rmsnorm_h2,
    // [3] first hgemm  <- captured by ncu
    convert_w_kernel<<<cblocks((long long)L_ * 2 * D_ * RWD), 256>>>(
        mixer_up, WMU, L_ * 2 * D_, D_, L_ * 2 * D_, L_ * 2 * D_, 0);
    embed_norm_kernel<<<BT_, 256>>>(tokens, embed, ln_in, X, MEM);

    const int scanThreads = B_ * S_ * DS_ * NC_;   // 16384

    for (int i = 0; i < L_; i++) {
        const float* ln1_i = ln1 + i * D_;
        const float* cw_i  = conv_w + (size_t)i * D_ * K_;
        const float* lnm_i = ln_mem + i * D_;
        const float* wg_i  = wg + (size_t)i * S_ * D_;
        const float* wv_i  = wv + (size_t)i * DS_ * D_;
        const float* rq_i  = rq + (size_t)i * S_ * D_;
        const float* ln2_i = ln2 + i * D_;

        const unsigned* wmu_i = WMU + (size_t)i * 2 * D_ * RWD;
        const unsigned* wmd_i = WMD + (size_t)i * D_ * RWD;
        const unsigned* wro_i = WRO + (size_t)i * D_ * RWRO;
        const unsigned* wff_i = WFF + (size_t)i * 2 * FF_ * RWD;
        const unsigned* wof_i = WOF + (size_t)i * D_ * RWFF;

        // mixer branch
        rmsnorm_h2_kernel<<<BT_, 256>>>(X, ln1_i, HN2);
        hgemm_kernel<0><<<dim3(2 * D_ / 64, BT_ / 128), 128, SMEM_T_>>>(
            HN2, wmu_i, nullptr, GV, BT_, 2 * D_, D_ / 64);

        if (i == 0) {
            convert_w_kernel<<<cblocks((long long)L_ * D_ * RWD), 256>>>(
                mixer_down, WMD, L_ * D_, D_, L_ * D_, L_ * D_, 0);
            convert_w_kernel<<<cblocks((long long)L_ * D_ * RWRO), 256>>>(
                ro, WRO, L_ * D_, S_ * DS_, L_ * D_, L_ * D_, 0);
            // INTERLEAVED Wgf/Wuf: dest row = 2*(l*FF+f) (+1 for Wuf)
            convert_w_kernel<<<cblocks((long long)L_ * FF_ * RWD), 256>>>(
                Wgf, WFF, L_ * FF_, D_, 1, 2, 0);
            convert_w_kernel<<<cblocks((long long)L_ * FF_ * RWD), 256>>>(
                Wuf, WFF, L_ * FF_, D_, 1, 2, 1);
            convert_w_kernel<<<cblocks((long long)L_ * D_ * RWFF), 256>>>(
                Wof, WOF, L_ * D_, FF_, L_ * D_, L_ * D_, 0);
            convert_w_kernel<<<cblocks((long long)V_ * RWD), 256>>>(
                embed, WEM, V_, D_, V_, V_, 0);
        }

        conv_gate_h2_kernel<<<BT_, 256>>>(GV, cw_i, CG2);
        hgemm_kernel<1><<<dim3(D_ / 64, BT_ / 128), 128, SMEM_T_>>>(
            CG2, wmd_i, X, X, BT_, D_, D_ / 64);

        // story memory branch
        rmsnorm_kernel<<<BT_, 256>>>(X, lnm_i, HN);
        smallproj_kernel<<<BT_, 256>>>(HN, wg_i, rq_i, wv_i, G, RQ, Vv);
        scan_pass1_kernel<<<scanThreads / 256, 256>>>(G, Vv, CHA, CHB);
        scan_pass2_kernel<<<1, B_ * S_ * DS_>>>(CHA, CHB, MEM, CST);
        scan_pass3_kernel<<<scanThreads / 256, 256>>>(G, Vv, CST, MS);
        rf_h2_kernel<<<BT_, 128>>>(RQ, MS, RF2);
        hgemm_kernel<1><<<dim3(D_ / 64, BT_ / 128), 128, SMEM_T_>>>(
            RF2, wro_i, X, X, BT_, D_, S_ * DS_ / 64);

        // FFN branch: interleaved gate|up GEMM with fused silu epilogue -> UP2 (half)
        rmsnorm_h2_kernel<<<BT_, 256>>>(X, ln2_i, HN2);
        hgemm_kernel<2><<<dim3(2 * FF_ / 64, BT_ / 128), 128, SMEM_T_>>>(
            HN2, wff_i, nullptr, (float*)UP2, BT_, 2 * FF_, D_ / 64);
        hgemm_kernel<1><<<dim3(D_ / 64, BT_ / 128), 128, SMEM_T_>>>(
            UP2, wof_i, X, X, BT_, D_, FF_ / 64);
    }

    // tied head
    rmsnorm_h2_kernel<<<BT_, 256>>>(X, ln_out, HN2);
    hgemm_kernel<0><<<dim3(V_ / 64, BT_ / 128), 128, SMEM_T_>>>(
        HN2, WEM, nullptr, out, BT_, V_, D_ / 64);
}

// round 17
// speedup vs baseline: 1.1039x; 1.0529x over previous
#include <cuda_runtime.h>
#include <cuda_fp16.h>
#include <stdint.h>
#include <math.h>

// ---------------- problem constants ----------------
#define V_  32000
#define D_  512
#define L_  6
#define FF_ 2048
#define T_  2048
#define B_  2
#define S_  8
#define DS_ 32
#define K_  15

#define BT_ (B_ * T_)          // 4096 tokens
#define NC_ 32                 // scan chunks
#define TC_ (T_ / NC_)         // 64 steps per chunk

// ---------------- device scratch (no allocations allowed) ----------------
__device__ float d_X  [BT_ * D_];
__device__ float d_HN [BT_ * D_];
__device__ float d_GV [BT_ * 2 * D_];
__device__ float d_G  [BT_ * S_];
__device__ float d_RQ [BT_ * S_];
__device__ float d_V  [BT_ * DS_];
__device__ float d_MS [BT_ * S_ * DS_];
__device__ float d_MEM[B_ * S_ * DS_];
__device__ float d_CHA[B_ * S_ * NC_];
__device__ float d_CHB[B_ * S_ * DS_ * NC_];
__device__ float d_CST[B_ * S_ * DS_ * NC_];

// fp16 operands, packed half2 words, row-major [row][K/2 words]
__device__ unsigned d_HN2[BT_ * D_ / 2];
__device__ unsigned d_CG2[BT_ * D_ / 2];
__device__ unsigned d_RF2[BT_ * S_ * DS_ / 2];
__device__ unsigned d_UP2[BT_ * FF_ / 2];
__device__ unsigned d_WMU[L_ * 2 * D_ * D_ / 2];
__device__ unsigned d_WMD[L_ * D_ * D_ / 2];
__device__ unsigned d_WRO[L_ * D_ * S_ * DS_ / 2];
__device__ unsigned d_WFF[L_ * 2 * FF_ * D_ / 2];   // INTERLEAVED: row 2f = Wgf_f, 2f+1 = Wuf_f
__device__ unsigned d_WOF[L_ * D_ * FF_ / 2];
__device__ unsigned d_WEM[V_ * D_ / 2];

// ---------------- fp16 helpers ----------------
__device__ __forceinline__ unsigned f2h2(float x0, float x1) {
    __half2 h = __floats2half2_rn(x0, x1);
    return *reinterpret_cast<unsigned*>(&h);
}

__device__ __forceinline__ void mma_f16(float* c, const unsigned* a, unsigned b0, unsigned b1) {
    asm volatile(
        "mma.sync.aligned.m16n8k16.row.col.f32.f16.f16.f32 "
        "{%0,%1,%2,%3}, {%4,%5,%6,%7}, {%8,%9}, {%0,%1,%2,%3};"
        : "+f"(c[0]), "+f"(c[1]), "+f"(c[2]), "+f"(c[3])
        : "r"(a[0]), "r"(a[1]), "r"(a[2]), "r"(a[3]), "r"(b0), "r"(b1));
}

__device__ __forceinline__ void cp16(unsigned saddr, const void* g)
{
    asm volatile("cp.async.cg.shared.global [%0], [%1], 16;" :: "r"(saddr), "l"(g));
}

// ---------------- fp16 tensor GEMM: C[M,N] = A @ W^T ----------------
// EPI: 0 = plain store, 1 = residual add, 2 = silu-combine adjacent column
// pairs (gate,up) -> __half store into C viewed as half[M][N/2].
#define ST_  36
#define AW_  (128 * ST_)           // 4608 words
#define BW_  (64 * ST_)            // 2304 words
#define STGW_ (AW_ + BW_)          // 6912 words per stage
#define SMEM_T_ (2 * STGW_ * 4)    // 55296 bytes

template<int EPI>
__global__ __launch_bounds__(128, 4)
void hgemm_kernel(const unsigned* __restrict__ A, const unsigned* __restrict__ W,
                  const float* __restrict__ R, float* __restrict__ C,
                  int M, int N, int KC)   // KC = K/64 chunks, KC >= 2
{
    extern __shared__ unsigned sm[];
    const unsigned sbase = (unsigned)__cvta_generic_to_shared(sm);
    const int tid = threadIdx.x, wid = tid >> 5, lane = tid & 31;
    const int grp = lane >> 2, kin = lane & 3;
    const int wm = wid * 32;
    const int row0 = blockIdx.y * 128, col0 = blockIdx.x * 64;
    const int Kw = KC * 32;   // words per row

    float acc[2][8][4];
#pragma unroll
    for (int i = 0; i < 2; i++)
#pragma unroll
        for (int j = 0; j < 8; j++)
#pragma unroll
            for (int r = 0; r < 4; r++) acc[i][j][r] = 0.f;

#define LOAD_STAGE(c) do {                                                    \
        const unsigned sb = sbase + (unsigned)(((c) & 1) * STGW_) * 4u;       \
        _Pragma("unroll")                                                     \
        for (int q = 0; q < 8; q++) {                                         \
            const int slot = tid + 128 * q;                                   \
            const int rr = slot >> 3, qq = slot & 7;                          \
            cp16(sb + (unsigned)(rr * ST_ + qq * 4) * 4u,                     \
                 A + (size_t)(row0 + rr) * Kw + (c) * 32 + qq * 4);           \
        }                                                                     \
        _Pragma("unroll")                                                     \
        for (int q = 0; q < 4; q++) {                                         \
            const int slot = tid + 128 * q;                                   \
            const int rr = slot >> 3, qq = slot & 7;                          \
            cp16(sb + (unsigned)(AW_ + rr * ST_ + qq * 4) * 4u,               \
                 W + (size_t)(col0 + rr) * Kw + (c) * 32 + qq * 4);           \
        }                                                                     \
        asm volatile("cp.async.commit_group;" ::: "memory");                  \
    } while (0)

    LOAD_STAGE(0);

    for (int c = 0; c < KC; c++) {
        if (c + 1 < KC) {
            LOAD_STAGE(c + 1);
            asm volatile("cp.async.wait_group 1;" ::: "memory");
        } else {
            asm volatile("cp.async.wait_group 0;" ::: "memory");
        }
        __syncthreads();

        const unsigned* sA = sm + (size_t)((c & 1) * STGW_);
        const unsigned* sB = sA + AW_;

#pragma unroll
        for (int s16 = 0; s16 < 4; s16++) {
            const int kc = s16 * 8 + kin;
            unsigned af[2][4], bf[8][2];
#pragma unroll
            for (int i = 0; i < 2; i++) {
                const int r0 = (wm + i * 16 + grp) * ST_;
                const int r1 = r0 + 8 * ST_;
                af[i][0] = sA[r0 + kc];
                af[i][1] = sA[r1 + kc];
                af[i][2] = sA[r0 + kc + 4];
                af[i][3] = sA[r1 + kc + 4];
            }
#pragma unroll
            for (int j = 0; j < 8; j++) {
                const int cb = (j * 8 + grp) * ST_;
                bf[j][0] = sB[cb + kc];
                bf[j][1] = sB[cb + kc + 4];
            }
#pragma unroll
            for (int j = 0; j < 8; j++)
#pragma unroll
                for (int i = 0; i < 2; i++)
                    mma_f16(acc[i][j], af[i], bf[j][0], bf[j][1]);
        }
        __syncthreads();
    }
#undef LOAD_STAGE

    // epilogue
    const int orow0 = row0 + wm + grp;
    const int ocol0 = col0 + 2 * kin;
    if (EPI == 2) {
        __half* H = reinterpret_cast<__half*>(C);
        const int hN = N >> 1;
#pragma unroll
        for (int i = 0; i < 2; i++) {
#pragma unroll
            for (int j = 0; j < 8; j++) {
                const int f = (ocol0 + j * 8) >> 1;
                float g0 = acc[i][j][0], u0 = acc[i][j][1];
                float g1 = acc[i][j][2], u1 = acc[i][j][3];
                H[(size_t)(orow0 + i * 16) * hN + f] =
                    __float2half_rn(g0 / (1.f + expf(-g0)) * u0);
                H[(size_t)(orow0 + i * 16 + 8) * hN + f] =
                    __float2half_rn(g1 / (1.f + expf(-g1)) * u1);
            }
        }
    } else {
#pragma unroll
        for (int i = 0; i < 2; i++) {
#pragma unroll
            for (int j = 0; j < 8; j++) {
                const size_t o0 = (size_t)(orow0 + i * 16) * N + ocol0 + j * 8;
                const size_t o1 = (size_t)(orow0 + i * 16 + 8) * N + ocol0 + j * 8;
                float2 v0 = make_float2(acc[i][j][0], acc[i][j][1]);
                float2 v1 = make_float2(acc[i][j][2], acc[i][j][3]);
                if (EPI == 1) {
                    float2 r0 = *reinterpret_cast<const float2*>(R + o0);
                    float2 r1 = *reinterpret_cast<const float2*>(R + o1);
                    v0.x += r0.x; v0.y += r0.y;
                    v1.x += r1.x; v1.y += r1.y;
                }
                *reinterpret_cast<float2*>(C + o0) = v0;
                *reinterpret_cast<float2*>(C + o1) = v1;
            }
        }
    }
}

// ---------------- weight converter: fp32 -> packed half2 words, row remap ----------------
__global__ __launch_bounds__(256) void convert_w_kernel(
    const float* __restrict__ src, unsigned* __restrict__ dst,
    int nRows, int K, int group, int dstride, int dbase)
{
    const int Kw = K >> 1;
    long long idx = (long long)blockIdx.x * 256 + threadIdx.x;
    if (idx >= (long long)nRows * Kw) return;
    int n = (int)(idx / Kw), w = (int)(idx - (long long)n * Kw);
    int dn = (n / group) * dstride + dbase + (n % group);
    dst[(size_t)dn * Kw + w] = f2h2(src[(size_t)n * K + 2 * w], src[(size_t)n * K + 2 * w + 1]);
}

// ---------------- embed gather + rmsnorm(ln_in) -> fp32 X; fused MEM zeroing ----------------
__global__ __launch_bounds__(256) void embed_norm_kernel(
    const int* __restrict__ tokens, const float* __restrict__ embed,
    const float* __restrict__ w, float* __restrict__ out, float* __restrict__ MEM)
{
    const int bt = blockIdx.x;
    const int tid = threadIdx.x;
    if (bt == 0) { MEM[tid] = 0.f; MEM[tid + 256] = 0.f; }
    const int tok = tokens[bt];
    const float* row = embed + (size_t)tok * D_;
    float x0 = row[tid], x1 = row[tid + 256];
    __shared__ float red[256];
    red[tid] = x0 * x0 + x1 * x1;
    __syncthreads();
    for (int s = 128; s > 0; s >>= 1) {
        if (tid < s) red[tid] += red[tid + s];
        __syncthreads();
    }
    float scale = rsqrtf(red[0] / (float)D_ + 1e-6f);
    out[bt * D_ + tid]       = x0 * scale * w[tid];
    out[bt * D_ + tid + 256] = x1 * scale * w[tid + 256];
}

// ---------------- rmsnorm -> fp32 (story-memory branch) ----------------
__global__ __launch_bounds__(256) void rmsnorm_kernel(
    const float* __restrict__ X, const float* __restrict__ w, float* __restrict__ O)
{
    const int bt = blockIdx.x;
    const int tid = threadIdx.x;
    float x0 = X[bt * D_ + tid], x1 = X[bt * D_ + tid + 256];
    __shared__ float red[256];
    red[tid] = x0 * x0 + x1 * x1;
    __syncthreads();
    for (int s = 128; s > 0; s >>= 1) {
        if (tid < s) red[tid] += red[tid + s];
        __syncthreads();
    }
    float scale = rsqrtf(red[0] / (float)D_ + 1e-6f);
    O[bt * D_ + tid]       = x0 * scale * w[tid];
    O[bt * D_ + tid + 256] = x1 * scale * w[tid + 256];
}

// ---------------- rmsnorm -> packed half2 (K=512 -> 256 words) ----------------
__global__ __launch_bounds__(256) void rmsnorm_h2_kernel(
    const float* __restrict__ X, const float* __restrict__ w, unsigned* __restrict__ O)
{
    const int bt = blockIdx.x;
    const int t = threadIdx.x;
    float x0 = X[(size_t)bt * D_ + 2 * t];
    float x1 = X[(size_t)bt * D_ + 2 * t + 1];
    __shared__ float red[256];
    red[t] = x0 * x0 + x1 * x1;
    __syncthreads();
    for (int s = 128; s > 0; s >>= 1) {
        if (t < s) red[t] += red[t + s];
        __syncthreads();
    }
    float sc = rsqrtf(red[0] / (float)D_ + 1e-6f);
    O[(size_t)bt * (D_ / 2) + t] = f2h2(x0 * sc * w[2 * t], x1 * sc * w[2 * t + 1]);
}

// ---------------- smem-tiled causal depthwise conv + gate -> packed half2 ----------------
// Tile: 64 tokens x 64 channels. val tile (incl. 14-row halo) loaded once to smem.
#define CT_ 64
#define CC_ 64
#define CH_ (K_ - 1)   // 14
__global__ __launch_bounds__(256) void conv_gate_tile_kernel(
    const float* __restrict__ GV, const float* __restrict__ cw, unsigned* __restrict__ CG2)
{
    __shared__ float sv[(CT_ + CH_) * CC_];   // 78*64 floats = 19968 B
    __shared__ float scw[CC_ * K_];           // 960 floats
    const int d0 = blockIdx.x * CC_;
    const int t0 = blockIdx.y * CT_;
    const int b  = blockIdx.z;
    const int tid = threadIdx.x;

    for (int i = tid; i < CC_ * K_; i += 256)
        scw[i] = cw[(size_t)(d0 + i / K_) * K_ + (i % K_)];
    for (int i = tid; i < (CT_ + CH_) * CC_; i += 256) {
        const int r = i / CC_, c = i - r * CC_;
        const int t = t0 - CH_ + r;
        sv[i] = (t >= 0) ? GV[(size_t)(b * T_ + t) * (2 * D_) + D_ + d0 + c] : 0.f;
    }
    __syncthreads();

#pragma unroll
    for (int q = 0; q < 8; q++) {
        const int o = tid + 256 * q;     // 0..2047
        const int tl = o >> 5;           // token in tile
        const int c0 = (o & 31) * 2;     // channel pair
        float s0 = 0.f, s1 = 0.f;
#pragma unroll
        for (int j = 0; j < K_; j++) {
            s0 += sv[(tl + j) * CC_ + c0]     * scw[c0 * K_ + j];
            s1 += sv[(tl + j) * CC_ + c0 + 1] * scw[(c0 + 1) * K_ + j];
        }
        const int bt = b * T_ + t0 + tl;
        float g0 = GV[(size_t)bt * (2 * D_) + d0 + c0];
        float g1 = GV[(size_t)bt * (2 * D_) + d0 + c0 + 1];
        CG2[(size_t)bt * (D_ / 2) + (d0 + c0) / 2] =
            f2h2(s0 / (1.f + expf(-g0)), s1 / (1.f + expf(-g1)));
    }
}

// ---------------- small projections ----------------
__global__ __launch_bounds__(256) void smallproj_kernel(
    const float* __restrict__ HN, const float* __restrict__ wg,
    const float* __restrict__ rqw, const float* __restrict__ wv,
    float* __restrict__ G, float* __restrict__ RQ, float* __restrict__ Vv)
{
    const int bt = blockIdx.x;
    const int tid = threadIdx.x;
    __shared__ float h[D_];
    h[tid] = HN[bt * D_ + tid];
    h[tid + 256] = HN[bt * D_ + tid + 256];
    __syncthreads();
    const int warp = tid >> 5, lane = tid & 31;
    for (int o = warp; o < S_ + S_ + DS_; o += 8) {
        const float* wrow;
        if (o < S_) wrow = wg + o * D_;
        else if (o < 2 * S_) wrow = rqw + (o - S_) * D_;
        else wrow = wv + (o - 2 * S_) * D_;
        float s = 0.f;
#pragma unroll
        for (int k = lane; k < D_; k += 32) s += h[k] * wrow[k];
#pragma unroll
        for (int off = 16; off > 0; off >>= 1) s += __shfl_down_sync(0xffffffffu, s, off);
        if (lane == 0) {
            if (o < S_) G[bt * S_ + o] = 1.f / (1.f + expf(-s));
            else if (o < 2 * S_) RQ[bt * S_ + (o - S_)] = s;
            else Vv[bt * DS_ + (o - 2 * S_)] = s;
        }
    }
}

// ---------------- chunked linear-recurrence scan ----------------
__global__ __launch_bounds__(256) void scan_pass1_kernel(
    const float* __restrict__ G, const float* __restrict__ Vv,
    float* __restrict__ CHA, float* __restrict__ CHB)
{
    const int idx = blockIdx.x * 256 + threadIdx.x;
    const int ds = idx % DS_;
    const int s  = (idx / DS_) % S_;
    const int c  = (idx / (DS_ * S_)) % NC_;
    const int b  = idx / (DS_ * S_ * NC_);
    float A = 1.f, Bv = 0.f;
    const int t0 = c * TC_;
    for (int t = t0; t < t0 + TC_; t++) {
        float g = G[(size_t)(b * T_ + t) * S_ + s];
        float a = 1.f - g;
        float bb = g * Vv[(size_t)(b * T_ + t) * DS_ + ds];
        A = a * A;
        Bv = a * Bv + bb;
    }
    CHB[((size_t)(b * S_ + s) * DS_ + ds) * NC_ + c] = Bv;
    if (ds == 0) CHA[(size_t)(b * S_ + s) * NC_ + c] = A;
}

__global__ __launch_bounds__(512) void scan_pass2_kernel(
    const float* __restrict__ CHA, const float* __restrict__ CHB,
    float* __restrict__ MEM, float* __restrict__ CST)
{
    const int idx = threadIdx.x;
    const int ds = idx % DS_;
    const int s  = (idx / DS_) % S_;
    const int b  = idx / (DS_ * S_);
    float st = MEM[idx];
    for (int c = 0; c < NC_; c++) {
        CST[((size_t)(b * S_ + s) * DS_ + ds) * NC_ + c] = st;
        float A = CHA[(size_t)(b * S_ + s) * NC_ + c];
        float Bv = CHB[((size_t)(b * S_ + s) * DS_ + ds) * NC_ + c];
        st = A * st + Bv;
    }
    MEM[idx] = st;
}

__global__ __launch_bounds__(256) void scan_pass3_kernel(
    const float* __restrict__ G, const float* __restrict__ Vv,
    const float* __restrict__ CST, float* __restrict__ MS)
{
    const int idx = blockIdx.x * 256 + threadIdx.x;
    const int ds = idx % DS_;
    const int s  = (idx / DS_) % S_;
    const int c  = (idx / (DS_ * S_)) % NC_;
    const int b  = idx / (DS_ * S_ * NC_);
    float m = CST[((size_t)(b * S_ + s) * DS_ + ds) * NC_ + c];
    const int t0 = c * TC_;
    for (int t = t0; t < t0 + TC_; t++) {
        float g = G[(size_t)(b * T_ + t) * S_ + s];
        float bb = g * Vv[(size_t)(b * T_ + t) * DS_ + ds];
        m = (1.f - g) * m + bb;
        MS[(size_t)(b * T_ + t) * (S_ * DS_) + s * DS_ + ds] = m;
    }
}

// ---------------- softmax read * mem_stack -> packed half2 (K=256 -> 128 words) ----------------
__global__ __launch_bounds__(128) void rf_h2_kernel(
    const float* __restrict__ RQ, const float* __restrict__ MS, unsigned* __restrict__ RF2)
{
    const int bt = blockIdx.x;
    const int t = threadIdx.x;   // word index 0..127
    __shared__ float q[S_];
    if (t < S_) q[t] = RQ[bt * S_ + t];
    __syncthreads();
    float mx = q[0];
#pragma unroll
    for (int i = 1; i < S_; i++) mx = fmaxf(mx, q[i]);
    float den = 0.f;
#pragma unroll
    for (int i = 0; i < S_; i++) den += expf(q[i] - mx);
    const int e0 = 2 * t;
    const int s = e0 >> 5;
    float wgt = expf(q[s] - mx) / den;
    RF2[(size_t)bt * 128 + t] =
        f2h2(wgt * MS[(size_t)bt * 256 + e0], wgt * MS[(size_t)bt * 256 + e0 + 1]);
}

// ---------------- host orchestration ----------------
static void* devptr(const void* symbol) {
    void* p = nullptr;
    cudaGetSymbolAddress(&p, symbol);
    return p;
}

static inline int cblocks(long long threads) { return (int)((threads + 255) / 256); }

extern "C" void kernel_launch(void* const* d_in, const int* in_sizes, int n_in,
                              void* d_out, int out_size)
{
    const int*   tokens    = (const int*)  d_in[0];
    const float* embed     = (const float*)d_in[1];
    const float* ln_in     = (const float*)d_in[2];
    const float* ln1       = (const float*)d_in[3];
    const float* mixer_up  = (const float*)d_in[4];
    const float* conv_w    = (const float*)d_in[5];
    const float* mixer_down= (const float*)d_in[6];
    const float* ln_mem    = (const float*)d_in[7];
    const float* wg        = (const float*)d_in[8];
    const float* wv        = (const float*)d_in[9];
    const float* rq        = (const float*)d_in[10];
    const float* ro        = (const float*)d_in[11];
    const float* ln2       = (const float*)d_in[12];
    const float* Wgf       = (const float*)d_in[13];
    const float* Wuf       = (const float*)d_in[14];
    const float* Wof       = (const float*)d_in[15];
    const float* ln_out    = (const float*)d_in[16];
    float* out = (float*)d_out;

    float* X   = (float*)devptr(d_X);
    float* HN  = (float*)devptr(d_HN);
    float* GV  = (float*)devptr(d_GV);
    float* G   = (float*)devptr(d_G);
    float* RQ  = (float*)devptr(d_RQ);
    float* Vv  = (float*)devptr(d_V);
    float* MS  = (float*)devptr(d_MS);
    float* MEM = (float*)devptr(d_MEM);
    float* CHA = (float*)devptr(d_CHA);
    float* CHB = (float*)devptr(d_CHB);
    float* CST = (float*)devptr(d_CST);

    unsigned* HN2 = (unsigned*)devptr(d_HN2);
    unsigned* CG2 = (unsigned*)devptr(d_CG2);
    unsigned* RF2 = (unsigned*)devptr(d_RF2);
    unsigned* UP2 = (unsigned*)devptr(d_UP2);
    unsigned* WMU = (unsigned*)devptr(d_WMU);
    unsigned* WMD = (unsigned*)devptr(d_WMD);
    unsigned* WRO = (unsigned*)devptr(d_WRO);
    unsigned* WFF = (unsigned*)devptr(d_WFF);
    unsigned* WOF = (unsigned*)devptr(d_WOF);
    unsigned* WEM = (unsigned*)devptr(d_WEM);

    cudaFuncSetAttribute(hgemm_kernel<0>, cudaFuncAttributeMaxDynamicSharedMemorySize, SMEM_T_);
    cudaFuncSetAttribute(hgemm_kernel<1>, cudaFuncAttributeMaxDynamicSharedMemorySize, SMEM_T_);
    cudaFuncSetAttribute(hgemm_kernel<2>, cudaFuncAttributeMaxDynamicSharedMemorySize, SMEM_T_);

    // packed words per row
    const size_t RWD  = D_ / 2;        // 256
    const size_t RWRO = S_ * DS_ / 2;  // 128
    const size_t RWFF = FF_ / 2;       // 1024

    // launch order: [0] convert WMU, [1] embed_norm(+MEM zero), [2] rmsnorm_h2,
    // [3] first hgemm  <- captured by ncu
    convert_w_kernel<<<cblocks((long long)L_ * 2 * D_ * RWD), 256>>>(
        mixer_up, WMU, L_ * 2 * D_, D_, L_ * 2 * D_, L_ * 2 * D_, 0);
    embed_norm_kernel<<<BT_, 256>>>(tokens, embed, ln_in, X, MEM);

    const int scanThreads = B_ * S_ * DS_ * NC_;   // 16384

    for (int i = 0; i < L_; i++) {
        const float* ln1_i = ln1 + i * D_;
        const float* cw_i  = conv_w + (size_t)i * D_ * K_;
        const float* lnm_i = ln_mem + i * D_;
        const float* wg_i  = wg + (size_t)i * S_ * D_;
        const float* wv_i  = wv + (size_t)i * DS_ * D_;
        const float* rq_i  = rq + (size_t)i * S_ * D_;
        const float* ln2_i = ln2 + i * D_;

        const unsigned* wmu_i = WMU + (size_t)i * 2 * D_ * RWD;
        const unsigned* wmd_i = WMD + (size_t)i * D_ * RWD;
        const unsigned* wro_i = WRO + (size_t)i * D_ * RWRO;
        const unsigned* wff_i = WFF + (size_t)i * 2 * FF_ * RWD;
        const unsigned* wof_i = WOF + (size_t)i * D_ * RWFF;

        // mixer branch
        rmsnorm_h2_kernel<<<BT_, 256>>>(X, ln1_i, HN2);
        hgemm_kernel<0><<<dim3(2 * D_ / 64, BT_ / 128), 128, SMEM_T_>>>(
            HN2, wmu_i, nullptr, GV, BT_, 2 * D_, D_ / 64);

        if (i == 0) {
            convert_w_kernel<<<cblocks((long long)L_ * D_ * RWD), 256>>>(
                mixer_down, WMD, L_ * D_, D_, L_ * D_, L_ * D_, 0);
            convert_w_kernel<<<cblocks((long long)L_ * D_ * RWRO), 256>>>(
                ro, WRO, L_ * D_, S_ * DS_, L_ * D_, L_ * D_, 0);
            // INTERLEAVED Wgf/Wuf: dest row = 2*(l*FF+f) (+1 for Wuf)
            convert_w_kernel<<<cblocks((long long)L_ * FF_ * RWD), 256>>>(
                Wgf, WFF, L_ * FF_, D_, 1, 2, 0);
            convert_w_kernel<<<cblocks((long long)L_ * FF_ * RWD), 256>>>(
                Wuf, WFF, L_ * FF_, D_, 1, 2, 1);
            convert_w_kernel<<<cblocks((long long)L_ * D_ * RWFF), 256>>>(
                Wof, WOF, L_ * D_, FF_, L_ * D_, L_ * D_, 0);
            convert_w_kernel<<<cblocks((long long)V_ * RWD), 256>>>(
                embed, WEM, V_, D_, V_, V_, 0);
        }

        conv_gate_tile_kernel<<<dim3(D_ / CC_, T_ / CT_, B_), 256>>>(GV, cw_i, CG2);
        hgemm_kernel<1><<<dim3(D_ / 64, BT_ / 128), 128, SMEM_T_>>>(
            CG2, wmd_i, X, X, BT_, D_, D_ / 64);

        // story memory branch
        rmsnorm_kernel<<<BT_, 256>>>(X, lnm_i, HN);
        smallproj_kernel<<<BT_, 256>>>(HN, wg_i, rq_i, wv_i, G, RQ, Vv);
        scan_pass1_kernel<<<scanThreads / 256, 256>>>(G, Vv, CHA, CHB);
        scan_pass2_kernel<<<1, B_ * S_ * DS_>>>(CHA, CHB, MEM, CST);
        scan_pass3_kernel<<<scanThreads / 256, 256>>>(G, Vv, CST, MS);
        rf_h2_kernel<<<BT_, 128>>>(RQ, MS, RF2);
        hgemm_kernel<1><<<dim3(D_ / 64, BT_ / 128), 128, SMEM_T_>>>(
            RF2, wro_i, X, X, BT_, D_, S_ * DS_ / 64);

        // FFN branch: interleaved gate|up GEMM with fused silu epilogue -> UP2 (half)
        rmsnorm_h2_kernel<<<BT_, 256>>>(X, ln2_i, HN2);
        hgemm_kernel<2><<<dim3(2 * FF_ / 64, BT_ / 128), 128, SMEM_T_>>>(
            HN2, wff_i, nullptr, (float*)UP2, BT_, 2 * FF_, D_ / 64);
        hgemm_kernel<1><<<dim3(D_ / 64, BT_ / 128), 128, SMEM_T_>>>(
            UP2, wof_i, X, X, BT_, D_, FF_ / 64);
    }

    // tied head
    rmsnorm_h2_kernel<<<BT_, 256>>>(X, ln_out, HN2);
    hgemm_kernel<0><<<dim3(V_ / 64, BT_ / 128), 128, SMEM_T_>>>(
        HN2, WEM, nullptr, out, BT_, V_, D_ / 64);
}